// round 16
// baseline (speedup 1.0000x reference)
#include <cuda_runtime.h>
#include <cuda_fp16.h>
#include <cstdint>

// ---------------- problem constants ----------------
constexpr int B  = 8;
constexpr int T  = 1024;
constexpr int D  = 1024;
constexpr int H  = 16;
constexpr int DH = 64;
constexpr float QSCALE = 0.125f * 1.44269504088896340736f;  // log2(e)/8
constexpr float EPS = 1e-13f;

// ---------------- scratch (device globals: fp16) ----------------
__device__ __half g_q[(size_t)B * H * T * DH];    // [B,H,T,DH]
__device__ __half g_k[(size_t)B * H * T * DH];    // [B,H,T,DH]
__device__ __half g_vt[(size_t)B * H * DH * T];   // [B,H,DH,T]  (pre-transposed)
__device__ __half g_ctx[(size_t)B * T * D];       // [B*T, D]
__device__ __half g_in_h[(size_t)B * T * D];
__device__ __half g_wqkv_h[(size_t)3 * D * D];
__device__ __half g_wout_h[(size_t)D * D];
__device__ __half g_adjm[(size_t)B * T * T];      // fp16 adj*mask, 16.8 MB

// ---------------- PTX helpers (base-arch only) ----------------
__device__ __forceinline__ uint32_t smem_u32(const void* p) {
    uint32_t a;
    asm("{ .reg .u64 t; cvta.to.shared.u64 t, %1; cvt.u32.u64 %0, t; }"
        : "=r"(a) : "l"(p));
    return a;
}

#define CP_ASYNC16(dst, src) \
    asm volatile("cp.async.cg.shared.global [%0], [%1], 16;" :: "r"(dst), "l"(src))
#define CP_COMMIT()  asm volatile("cp.async.commit_group;" ::: "memory")
#define CP_WAIT(n)   asm volatile("cp.async.wait_group %0;" :: "n"(n) : "memory")

#define LDMATRIX_X4(r0, r1, r2, r3, addr) \
    asm volatile("ldmatrix.sync.aligned.m8n8.x4.shared.b16 {%0,%1,%2,%3}, [%4];" \
        : "=r"(r0), "=r"(r1), "=r"(r2), "=r"(r3) : "r"(addr))

__device__ __forceinline__ float ex2(float x) {
    float r;
    asm("ex2.approx.f32 %0, %1;" : "=f"(r) : "f"(x));
    return r;
}

__device__ __forceinline__ void mma_f16(float* c, const uint32_t* a,
                                        uint32_t b0, uint32_t b1) {
    asm volatile(
        "mma.sync.aligned.m16n8k16.row.col.f32.f16.f16.f32 "
        "{%0,%1,%2,%3}, {%4,%5,%6,%7}, {%8,%9}, {%0,%1,%2,%3};"
        : "+f"(c[0]), "+f"(c[1]), "+f"(c[2]), "+f"(c[3])
        : "r"(a[0]), "r"(a[1]), "r"(a[2]), "r"(a[3]), "r"(b0), "r"(b1));
}

// ============================================================================
// fp32 -> fp16 convert pass
// ============================================================================
__global__ void __launch_bounds__(256)
f2h_kernel(const float4* __restrict__ src, __half2* __restrict__ dst, int n4)
{
    const int i = blockIdx.x * 256 + threadIdx.x;
    if (i < n4) {
        const float4 v = src[i];
        dst[2 * i + 0] = __floats2half2_rn(v.x, v.y);
        dst[2 * i + 1] = __floats2half2_rn(v.z, v.w);
    }
}

// adjm = fp16(adj * mask[b,k])  — folds the mask into the exponent operand
__global__ void __launch_bounds__(256)
adjm_kernel(const float4* __restrict__ adj, const float* __restrict__ mask,
            __half2* __restrict__ dst)
{
    const int i = blockIdx.x * 256 + threadIdx.x;      // float4 index
    const int n4 = (B * T * T) / 4;
    if (i < n4) {
        const float4 v = adj[i];
        const int elem = i * 4;
        const int bb = elem >> 20;                      // / (T*T)
        const int k  = elem & (T - 1);                  // % T  (4-aligned)
        const float m0 = mask[bb * T + k + 0];
        const float m1 = mask[bb * T + k + 1];
        const float m2 = mask[bb * T + k + 2];
        const float m3 = mask[bb * T + k + 3];
        dst[2 * i + 0] = __floats2half2_rn(v.x * m0, v.y * m1);
        dst[2 * i + 1] = __floats2half2_rn(v.z * m2, v.w * m3);
    }
}

// ============================================================================
// fp16 mma.sync GEMM (R15 winner): 128x128 block, 256 thr, 8 warps 64x32,
// K-chunks of 64 halves, 3-stage cp.async, 2 CTAs/SM.
// ============================================================================
constexpr int GBK = 64;
constexpr int G_TILE  = 128 * 128;
constexpr int G_STAGE = 2 * G_TILE;
constexpr int GEMM_SMEM_BYTES = 3 * G_STAGE;    // 96 KB

__device__ __forceinline__ void load_chunk(uint32_t sA, uint32_t sB,
                                           const __half* __restrict__ Ab,
                                           const __half* __restrict__ Wb,
                                           int K, int k0) {
    const int tid = threadIdx.x;
#pragma unroll
    for (int it = 0; it < 4; it++) {
        const int idx = it * 256 + tid;
        const int r = idx >> 3;
        const int s = idx & 7;
        const uint32_t off = (uint32_t)r * 128u + (((uint32_t)s * 16u) ^ (((uint32_t)r & 7u) << 4));
        CP_ASYNC16(sA + off, Ab + (size_t)r * K + k0 + s * 8);
    }
#pragma unroll
    for (int it = 0; it < 4; it++) {
        const int idx = it * 256 + tid;
        const int r = idx >> 3;
        const int s = idx & 7;
        const uint32_t off = (uint32_t)r * 128u + (((uint32_t)s * 16u) ^ (((uint32_t)r & 7u) << 4));
        CP_ASYNC16(sB + off, Wb + (size_t)r * K + k0 + s * 8);
    }
}

template <int MODE>
__global__ void __launch_bounds__(256, 2)
gemm_mma_kernel(const __half* __restrict__ A, const __half* __restrict__ W,
                const float* __restrict__ bias, float* __restrict__ C,
                int K, int Ntot)
{
    extern __shared__ __align__(1024) char smem[];
    const uint32_t sbase = smem_u32(smem);
    const int tid  = threadIdx.x;
    const int wid  = tid >> 5;
    const int lane = tid & 31;

    const int m0 = blockIdx.y * 128;
    const int n0 = blockIdx.x * 128;

    const __half* Asrc = (MODE == 1) ? (const __half*)g_ctx : A;
    const __half* Ab = Asrc + (size_t)m0 * K;
    const __half* Wb = W    + (size_t)n0 * K;

    uint32_t sA[3], sB[3];
#pragma unroll
    for (int s = 0; s < 3; s++) {
        sA[s] = sbase + s * G_STAGE;
        sB[s] = sA[s] + G_TILE;
    }

    const int wm = (wid >> 2) * 64;
    const int wn = (wid & 3) * 32;

    const int arow       = wm + (lane & 15);
    const uint32_t aoff  = (uint32_t)arow * 128u;
    const uint32_t aswz  = ((uint32_t)arow & 7u) << 4;
    const uint32_t akhi  = (uint32_t)(lane & 16);
    const int      b_rl  = (lane & 7) + ((lane & 16) >> 1);
    const uint32_t bkhi  = (uint32_t)((lane & 8) << 1);

    float acc[4][4][4];
#pragma unroll
    for (int i = 0; i < 4; i++)
#pragma unroll
        for (int j = 0; j < 4; j++)
#pragma unroll
            for (int e = 0; e < 4; e++) acc[i][j][e] = 0.f;

    const int NC = K / GBK;

    load_chunk(sA[0], sB[0], Ab, Wb, K, 0);
    CP_COMMIT();
    load_chunk(sA[1], sB[1], Ab, Wb, K, GBK);
    CP_COMMIT();

    int st = 0;
    for (int i = 0; i < NC; i++) {
        CP_WAIT(1);
        __syncthreads();

        const int pst = (st + 2 >= 3) ? st + 2 - 3 : st + 2;
        if (i + 2 < NC)
            load_chunk(sA[pst], sB[pst], Ab, Wb, K, (i + 2) * GBK);
        CP_COMMIT();

        const uint32_t aB = sA[st];
        const uint32_t bB = sB[st];

#pragma unroll
        for (int ks = 0; ks < 4; ks++) {
            const uint32_t kb = (uint32_t)ks * 32u;
            uint32_t afr[4][4];
#pragma unroll
            for (int tm = 0; tm < 4; tm++) {
                const uint32_t addr = aB + aoff + (uint32_t)tm * 2048u + ((kb + akhi) ^ aswz);
                LDMATRIX_X4(afr[tm][0], afr[tm][1], afr[tm][2], afr[tm][3], addr);
            }
            uint32_t bfr[2][4];
#pragma unroll
            for (int tp = 0; tp < 2; tp++) {
                const int brow = wn + tp * 16 + b_rl;
                const uint32_t addr = bB + (uint32_t)brow * 128u +
                                      ((kb + bkhi) ^ (((uint32_t)brow & 7u) << 4));
                LDMATRIX_X4(bfr[tp][0], bfr[tp][1], bfr[tp][2], bfr[tp][3], addr);
            }
#pragma unroll
            for (int tm = 0; tm < 4; tm++)
#pragma unroll
                for (int tn = 0; tn < 4; tn++)
                    mma_f16(acc[tm][tn], afr[tm],
                            bfr[tn >> 1][(tn & 1) * 2 + 0],
                            bfr[tn >> 1][(tn & 1) * 2 + 1]);
        }
        st = (st + 1 >= 3) ? 0 : st + 1;
    }

#pragma unroll
    for (int tm = 0; tm < 4; tm++) {
#pragma unroll
        for (int tn = 0; tn < 4; tn++) {
            const int col = n0 + wn + tn * 8 + (lane & 3) * 2;
            const float bx = bias[col], by = bias[col + 1];
#pragma unroll
            for (int half_i = 0; half_i < 2; half_i++) {
                const int row = m0 + wm + tm * 16 + (lane >> 2) + half_i * 8;
                const float vx = acc[tm][tn][half_i * 2 + 0] + bx;
                const float vy = acc[tm][tn][half_i * 2 + 1] + by;
                if (MODE == 0) {
                    const int sel = col >> 10;
                    const int bb = row >> 10;
                    const int t  = row & 1023;
                    const int hh = (col & 1023) >> 6;
                    const int d  = col & 63;
                    if (sel == 2) {
                        __half* vt = g_vt + (size_t)(bb * H + hh) * DH * T;
                        vt[(size_t)d * T + t]       = __float2half_rn(vx);
                        vt[(size_t)(d + 1) * T + t] = __float2half_rn(vy);
                    } else {
                        __half* dst = (sel == 0) ? g_q : g_k;
                        *(__half2*)&dst[((size_t)(bb * H + hh) * T + t) * DH + d] =
                            __floats2half2_rn(vx, vy);
                    }
                } else {
                    float2 v; v.x = vx; v.y = vy;
                    *(float2*)&C[(size_t)row * Ntot + col] = v;
                }
            }
        }
    }
}

// ============================================================================
// Fused flash attention (R14 structure): fp16 mma.sync, register-resident P,
// 2-buffer K/V double-buffering, fp16 adjm (mask pre-folded).
// ============================================================================
constexpr int AQT = 128;
constexpr int AKT = 64;
constexpr int AOFF_Q  = 0;                      // [128 q][64 h] fp16
constexpr int AOFF_K0 = AOFF_Q  + 128 * 128;
constexpr int AOFF_K1 = AOFF_K0 + 64 * 128;
constexpr int AOFF_V0 = AOFF_K1 + 64 * 128;
constexpr int AOFF_V1 = AOFF_V0 + 64 * 128;
constexpr int AOFF_M0 = AOFF_V1 + 64 * 128;     // 64 floats
constexpr int AOFF_M1 = AOFF_M0 + 256;
constexpr int ATTN_SMEM_BYTES = AOFF_M1 + 256;  // 49,920 B

__device__ __forceinline__ void attn_load_tile(
    uint32_t sKb, uint32_t sVb, uint32_t sMb,
    const __half* __restrict__ kbase, const __half* __restrict__ vtbase,
    const float* __restrict__ mrow, int kk0, int tid)
{
#pragma unroll
    for (int it = 0; it < 2; it++) {
        const int idx = it * 256 + tid;
        const int r = idx >> 3, s = idx & 7;
        CP_ASYNC16(sKb + (uint32_t)r * 128u + (((uint32_t)s * 16u) ^ (((uint32_t)r & 7u) << 4)),
                   kbase + (size_t)(kk0 + r) * DH + s * 8);
    }
#pragma unroll
    for (int it = 0; it < 2; it++) {
        const int idx = it * 256 + tid;
        const int r = idx >> 3, s = idx & 7;
        CP_ASYNC16(sVb + (uint32_t)r * 128u + (((uint32_t)s * 16u) ^ (((uint32_t)r & 7u) << 4)),
                   vtbase + (size_t)r * T + kk0 + s * 8);
    }
    if (tid < 16)
        CP_ASYNC16(sMb + (uint32_t)tid * 16u, mrow + kk0 + tid * 4);
}

__global__ void __launch_bounds__(256, 2)
attn_mma_kernel(const float* __restrict__ mask)
{
    extern __shared__ __align__(1024) char smc[];

    const int b   = blockIdx.z;
    const int h   = blockIdx.y;
    const int q0g = blockIdx.x * AQT;
    const int tid = threadIdx.x;
    const int wid = tid >> 5;
    const int lane = tid & 31;
    const int q0  = wid * 16;

    const __half* qptr   = g_q  + ((size_t)(b * H + h) * T + q0g) * DH;
    const __half* kbase  = g_k  + (size_t)(b * H + h) * T * DH;
    const __half* vtbase = g_vt + (size_t)(b * H + h) * DH * T;
    const __half* aptr   = g_adjm + ((size_t)b * T + q0g) * T;
    const float*  mrow   = mask + (size_t)b * T;

    const uint32_t sbase = smem_u32(smc);
    const uint32_t sQ = sbase + AOFF_Q;
    const uint32_t sK[2] = { sbase + AOFF_K0, sbase + AOFF_K1 };
    const uint32_t sV[2] = { sbase + AOFF_V0, sbase + AOFF_V1 };

    // ---- load Q once: fp16 -> scale by log2(e)/8 -> fp16, swizzled rows ----
#pragma unroll
    for (int it = 0; it < 4; it++) {
        const int idx = it * 256 + tid;
        const int r = idx >> 3, s = idx & 7;
        const __half2* src = (const __half2*)(qptr + (size_t)r * DH + s * 8);
        uint32_t out[4];
#pragma unroll
        for (int j = 0; j < 4; j++) {
            float2 f = __half22float2(src[j]);
            __half2 hv = __floats2half2_rn(f.x * QSCALE, f.y * QSCALE);
            out[j] = *(uint32_t*)&hv;
        }
        *(uint4*)(smc + r * 128 + (((uint32_t)s * 16u) ^ (((uint32_t)r & 7u) << 4))) =
            make_uint4(out[0], out[1], out[2], out[3]);
    }

    attn_load_tile(sK[0], sV[0], sbase + AOFF_M0, kbase, vtbase, mrow, 0, tid);
    CP_COMMIT();

    const int      a_row    = q0 + (lane & 15);
    const uint32_t a_off    = (uint32_t)a_row * 128u;
    const uint32_t a_swz    = ((uint32_t)a_row & 7u) << 4;
    const uint32_t a_khi    = (uint32_t)(lane & 16);
    const int      b_rl     = (lane & 7) + ((lane & 16) >> 1);
    const uint32_t b_khi    = (uint32_t)((lane & 8) << 1);

    const int rq_lo = q0 + (lane >> 2);
    const int ccol0 = (lane & 3) * 2;

    __syncthreads();   // Q stores visible

    // ---- hoist Q fragments (4 x k16 over DH=64) ----
    uint32_t qfr[4][4];
#pragma unroll
    for (int ks = 0; ks < 4; ks++) {
        LDMATRIX_X4(qfr[ks][0], qfr[ks][1], qfr[ks][2], qfr[ks][3],
                    sQ + a_off + (((uint32_t)ks * 32u + a_khi) ^ a_swz));
    }

    float oacc[8][4];
#pragma unroll
    for (int tn = 0; tn < 8; tn++)
#pragma unroll
        for (int e = 0; e < 4; e++) oacc[tn][e] = 0.f;
    float l1[2] = { 0.f, 0.f };
    float l2[2] = { 0.f, 0.f };

    constexpr int NT = T / AKT;

    for (int kt = 0; kt < NT; kt++) {
        const int cur = kt & 1;
        const int kk0 = kt * AKT;

        CP_WAIT(0);
        __syncthreads();

        // adjm (fp16, mask folded) -> registers early
        __half2 areg[2][8];
#pragma unroll
        for (int hh = 0; hh < 2; hh++) {
            const __half* arow = aptr + (size_t)(rq_lo + 8 * hh) * T + kk0 + ccol0;
#pragma unroll
            for (int tn = 0; tn < 8; tn++)
                areg[hh][tn] = *(const __half2*)(arow + tn * 8);
        }

        if (kt + 1 < NT) {
            attn_load_tile(sK[1 - cur], sV[1 - cur],
                           sbase + (cur ? AOFF_M0 : AOFF_M1),
                           kbase, vtbase, mrow, (kt + 1) * AKT, tid);
        }
        CP_COMMIT();

        const uint32_t sKb = sK[cur];
        const uint32_t sVb = sV[cur];
        const float* Ms = (const float*)(smc + (cur ? AOFF_M1 : AOFF_M0));

        float2 mreg[8];
#pragma unroll
        for (int tn = 0; tn < 8; tn++)
            mreg[tn] = *(const float2*)&Ms[tn * 8 + ccol0];

        // ---- S = Q @ K^T : 4 k16-steps, 8 n-tiles ----
        float sacc[8][4];
#pragma unroll
        for (int tn = 0; tn < 8; tn++)
#pragma unroll
            for (int e = 0; e < 4; e++) sacc[tn][e] = 0.f;

#pragma unroll
        for (int ks = 0; ks < 4; ks++) {
            const uint32_t kb = (uint32_t)ks * 32u;
            uint32_t kf[4][4];
#pragma unroll
            for (int tp = 0; tp < 4; tp++) {
                const uint32_t row = (uint32_t)(tp * 16 + b_rl);
                LDMATRIX_X4(kf[tp][0], kf[tp][1], kf[tp][2], kf[tp][3],
                            sKb + row * 128u + ((kb + b_khi) ^ ((row & 7u) << 4)));
            }
#pragma unroll
            for (int tn = 0; tn < 8; tn++)
                mma_f16(sacc[tn], qfr[ks],
                        kf[tn >> 1][(tn & 1) * 2 + 0],
                        kf[tn >> 1][(tn & 1) * 2 + 1]);
        }

        // ---- softmax -> P in REGISTERS -> PV mma (per k16 group g) ----
#pragma unroll
        for (int g = 0; g < 4; g++) {
            uint32_t pa[4];
#pragma unroll
            for (int u = 0; u < 2; u++) {
                const int tn = g * 2 + u;
#pragma unroll
                for (int hh = 0; hh < 2; hh++) {
                    const float2 af = __half22float2(areg[hh][tn]);
                    const float p0 = ex2(sacc[tn][2 * hh + 0] * af.x);
                    const float p1 = ex2(sacc[tn][2 * hh + 1] * af.y);
                    const float pm0 = p0 * mreg[tn].x;
                    const float pm1 = p1 * mreg[tn].y;
                    l2[hh] += p0 + p1;
                    l1[hh] += pm0 + pm1;
                    const __half2 pw = __floats2half2_rn(pm0, pm1);
                    pa[u * 2 + hh] = *(const uint32_t*)&pw;
                }
            }

            const uint32_t kb = (uint32_t)g * 32u;
            uint32_t vf[4][4];
#pragma unroll
            for (int tp = 0; tp < 4; tp++) {
                const uint32_t row = (uint32_t)(tp * 16 + b_rl);
                LDMATRIX_X4(vf[tp][0], vf[tp][1], vf[tp][2], vf[tp][3],
                            sVb + row * 128u + ((kb + b_khi) ^ ((row & 7u) << 4)));
            }
#pragma unroll
            for (int tn = 0; tn < 8; tn++)
                mma_f16(oacc[tn], pa,
                        vf[tn >> 1][(tn & 1) * 2 + 0],
                        vf[tn >> 1][(tn & 1) * 2 + 1]);
        }
    }

    // ---- one-time l1/l2 reduction over the 4-lane row group ----
#pragma unroll
    for (int hh = 0; hh < 2; hh++) {
        l1[hh] += __shfl_xor_sync(0xffffffffu, l1[hh], 1);
        l1[hh] += __shfl_xor_sync(0xffffffffu, l1[hh], 2);
        l2[hh] += __shfl_xor_sync(0xffffffffu, l2[hh], 1);
        l2[hh] += __shfl_xor_sync(0xffffffffu, l2[hh], 2);
    }

    // ---- normalize, fp16, write ctx ----
#pragma unroll
    for (int hh = 0; hh < 2; hh++) {
        const float inv = 1.0f / (l1[hh] + EPS * l2[hh]);
        const int gq = q0g + rq_lo + 8 * hh;
#pragma unroll
        for (int tn = 0; tn < 8; tn++) {
            const int d = tn * 8 + ccol0;
            *(__half2*)&g_ctx[(size_t)(b * T + gq) * D + h * DH + d] =
                __floats2half2_rn(oacc[tn][2 * hh + 0] * inv,
                                  oacc[tn][2 * hh + 1] * inv);
        }
    }
}

// ============================================================================
// launch
// ============================================================================
extern "C" void kernel_launch(void* const* d_in, const int* in_sizes, int n_in,
                              void* d_out, int out_size)
{
    (void)in_sizes; (void)n_in; (void)out_size;
    const float* inputs = (const float*)d_in[0];
    const float* mask   = (const float*)d_in[1];
    const float* adj    = (const float*)d_in[2];
    const float* W_qkv  = (const float*)d_in[3];
    const float* b_qkv  = (const float*)d_in[4];
    const float* W_out  = (const float*)d_in[5];
    const float* b_out  = (const float*)d_in[6];
    float* out = (float*)d_out;

    cudaFuncSetAttribute(gemm_mma_kernel<0>,
                         cudaFuncAttributeMaxDynamicSharedMemorySize,
                         GEMM_SMEM_BYTES);
    cudaFuncSetAttribute(gemm_mma_kernel<1>,
                         cudaFuncAttributeMaxDynamicSharedMemorySize,
                         GEMM_SMEM_BYTES);
    cudaFuncSetAttribute(attn_mma_kernel,
                         cudaFuncAttributeMaxDynamicSharedMemorySize,
                         ATTN_SMEM_BYTES);

    __half *p_in_h, *p_wqkv_h, *p_wout_h, *p_adjm;
    cudaGetSymbolAddress((void**)&p_in_h,   g_in_h);
    cudaGetSymbolAddress((void**)&p_wqkv_h, g_wqkv_h);
    cudaGetSymbolAddress((void**)&p_wout_h, g_wout_h);
    cudaGetSymbolAddress((void**)&p_adjm,   g_adjm);

    dim3 blk256(256);

    // fp32 -> fp16 conversion + adj*mask fold
    {
        const int n4_in   = (B * T * D) / 4;
        const int n4_wqkv = (3 * D * D) / 4;
        const int n4_wout = (D * D) / 4;
        const int n4_adj  = (B * T * T) / 4;
        f2h_kernel<<<(n4_in   + 255) / 256, blk256>>>((const float4*)inputs, (__half2*)p_in_h,   n4_in);
        f2h_kernel<<<(n4_wqkv + 255) / 256, blk256>>>((const float4*)W_qkv,  (__half2*)p_wqkv_h, n4_wqkv);
        f2h_kernel<<<(n4_wout + 255) / 256, blk256>>>((const float4*)W_out,  (__half2*)p_wout_h, n4_wout);
        adjm_kernel<<<(n4_adj + 255) / 256, blk256>>>((const float4*)adj, mask, (__half2*)p_adjm);
    }

    // QKV projection: M=8192, N=3072, K=1024 (fp16 mma.sync)
    gemm_mma_kernel<0><<<dim3((3 * D) / 128, (B * T) / 128), blk256, GEMM_SMEM_BYTES>>>(
        p_in_h, p_wqkv_h, b_qkv, nullptr, D, 3 * D);

    // fused attention (fp16 mma.sync, register-resident P, fp16 adjm)
    attn_mma_kernel<<<dim3(T / AQT, H, B), blk256, ATTN_SMEM_BYTES>>>(mask);

    // output projection: M=8192, N=1024, K=1024 (fp16 mma.sync)
    gemm_mma_kernel<1><<<dim3(D / 128, (B * T) / 128), blk256, GEMM_SMEM_BYTES>>>(
        nullptr, p_wout_h, b_out, out, D, D);
}

// round 17
// speedup vs baseline: 1.0352x; 1.0352x over previous
#include <cuda_runtime.h>
#include <cuda_fp16.h>
#include <cstdint>

// ---------------- problem constants ----------------
constexpr int B  = 8;
constexpr int T  = 1024;
constexpr int D  = 1024;
constexpr int H  = 16;
constexpr int DH = 64;
constexpr float QSCALE = 0.125f * 1.44269504088896340736f;  // log2(e)/8
constexpr float EPS = 1e-13f;

// ---------------- scratch (device globals: fp16) ----------------
__device__ __half g_q[(size_t)B * H * T * DH];    // [B,H,T,DH]
__device__ __half g_k[(size_t)B * H * T * DH];    // [B,H,T,DH]
__device__ __half g_vt[(size_t)B * H * DH * T];   // [B,H,DH,T]  (pre-transposed)
__device__ __half g_ctx[(size_t)B * T * D];       // [B*T, D]
__device__ __half g_in_h[(size_t)B * T * D];
__device__ __half g_wqkv_h[(size_t)3 * D * D];
__device__ __half g_wout_h[(size_t)D * D];

// ---------------- PTX helpers (base-arch only) ----------------
__device__ __forceinline__ uint32_t smem_u32(const void* p) {
    uint32_t a;
    asm("{ .reg .u64 t; cvta.to.shared.u64 t, %1; cvt.u32.u64 %0, t; }"
        : "=r"(a) : "l"(p));
    return a;
}

#define CP_ASYNC16(dst, src) \
    asm volatile("cp.async.cg.shared.global [%0], [%1], 16;" :: "r"(dst), "l"(src))
#define CP_COMMIT()  asm volatile("cp.async.commit_group;" ::: "memory")
#define CP_WAIT(n)   asm volatile("cp.async.wait_group %0;" :: "n"(n) : "memory")

#define LDMATRIX_X4(r0, r1, r2, r3, addr) \
    asm volatile("ldmatrix.sync.aligned.m8n8.x4.shared.b16 {%0,%1,%2,%3}, [%4];" \
        : "=r"(r0), "=r"(r1), "=r"(r2), "=r"(r3) : "r"(addr))

__device__ __forceinline__ float ex2(float x) {
    float r;
    asm("ex2.approx.f32 %0, %1;" : "=f"(r) : "f"(x));
    return r;
}

__device__ __forceinline__ void mma_f16(float* c, const uint32_t* a,
                                        uint32_t b0, uint32_t b1) {
    asm volatile(
        "mma.sync.aligned.m16n8k16.row.col.f32.f16.f16.f32 "
        "{%0,%1,%2,%3}, {%4,%5,%6,%7}, {%8,%9}, {%0,%1,%2,%3};"
        : "+f"(c[0]), "+f"(c[1]), "+f"(c[2]), "+f"(c[3])
        : "r"(a[0]), "r"(a[1]), "r"(a[2]), "r"(a[3]), "r"(b0), "r"(b1));
}

// ============================================================================
// fp32 -> fp16 convert pass
// ============================================================================
__global__ void __launch_bounds__(256)
f2h_kernel(const float4* __restrict__ src, __half2* __restrict__ dst, int n4)
{
    const int i = blockIdx.x * 256 + threadIdx.x;
    if (i < n4) {
        const float4 v = src[i];
        dst[2 * i + 0] = __floats2half2_rn(v.x, v.y);
        dst[2 * i + 1] = __floats2half2_rn(v.z, v.w);
    }
}

// ============================================================================
// fp16 mma.sync GEMM (R15 winner): 128x128 block, 256 thr, 8 warps 64x32,
// K-chunks of 64 halves, 3-stage cp.async, 2 CTAs/SM.
// ============================================================================
constexpr int GBK = 64;
constexpr int G_TILE  = 128 * 128;
constexpr int G_STAGE = 2 * G_TILE;
constexpr int GEMM_SMEM_BYTES = 3 * G_STAGE;    // 96 KB

__device__ __forceinline__ void load_chunk(uint32_t sA, uint32_t sB,
                                           const __half* __restrict__ Ab,
                                           const __half* __restrict__ Wb,
                                           int K, int k0) {
    const int tid = threadIdx.x;
#pragma unroll
    for (int it = 0; it < 4; it++) {
        const int idx = it * 256 + tid;
        const int r = idx >> 3;
        const int s = idx & 7;
        const uint32_t off = (uint32_t)r * 128u + (((uint32_t)s * 16u) ^ (((uint32_t)r & 7u) << 4));
        CP_ASYNC16(sA + off, Ab + (size_t)r * K + k0 + s * 8);
    }
#pragma unroll
    for (int it = 0; it < 4; it++) {
        const int idx = it * 256 + tid;
        const int r = idx >> 3;
        const int s = idx & 7;
        const uint32_t off = (uint32_t)r * 128u + (((uint32_t)s * 16u) ^ (((uint32_t)r & 7u) << 4));
        CP_ASYNC16(sB + off, Wb + (size_t)r * K + k0 + s * 8);
    }
}

template <int MODE>
__global__ void __launch_bounds__(256, 2)
gemm_mma_kernel(const __half* __restrict__ A, const __half* __restrict__ W,
                const float* __restrict__ bias, float* __restrict__ C,
                int K, int Ntot)
{
    extern __shared__ __align__(1024) char smem[];
    const uint32_t sbase = smem_u32(smem);
    const int tid  = threadIdx.x;
    const int wid  = tid >> 5;
    const int lane = tid & 31;

    const int m0 = blockIdx.y * 128;
    const int n0 = blockIdx.x * 128;

    const __half* Asrc = (MODE == 1) ? (const __half*)g_ctx : A;
    const __half* Ab = Asrc + (size_t)m0 * K;
    const __half* Wb = W    + (size_t)n0 * K;

    uint32_t sA[3], sB[3];
#pragma unroll
    for (int s = 0; s < 3; s++) {
        sA[s] = sbase + s * G_STAGE;
        sB[s] = sA[s] + G_TILE;
    }

    const int wm = (wid >> 2) * 64;
    const int wn = (wid & 3) * 32;

    const int arow       = wm + (lane & 15);
    const uint32_t aoff  = (uint32_t)arow * 128u;
    const uint32_t aswz  = ((uint32_t)arow & 7u) << 4;
    const uint32_t akhi  = (uint32_t)(lane & 16);
    const int      b_rl  = (lane & 7) + ((lane & 16) >> 1);
    const uint32_t bkhi  = (uint32_t)((lane & 8) << 1);

    float acc[4][4][4];
#pragma unroll
    for (int i = 0; i < 4; i++)
#pragma unroll
        for (int j = 0; j < 4; j++)
#pragma unroll
            for (int e = 0; e < 4; e++) acc[i][j][e] = 0.f;

    const int NC = K / GBK;

    load_chunk(sA[0], sB[0], Ab, Wb, K, 0);
    CP_COMMIT();
    load_chunk(sA[1], sB[1], Ab, Wb, K, GBK);
    CP_COMMIT();

    int st = 0;
    for (int i = 0; i < NC; i++) {
        CP_WAIT(1);
        __syncthreads();

        const int pst = (st + 2 >= 3) ? st + 2 - 3 : st + 2;
        if (i + 2 < NC)
            load_chunk(sA[pst], sB[pst], Ab, Wb, K, (i + 2) * GBK);
        CP_COMMIT();

        const uint32_t aB = sA[st];
        const uint32_t bB = sB[st];

#pragma unroll
        for (int ks = 0; ks < 4; ks++) {
            const uint32_t kb = (uint32_t)ks * 32u;
            uint32_t afr[4][4];
#pragma unroll
            for (int tm = 0; tm < 4; tm++) {
                const uint32_t addr = aB + aoff + (uint32_t)tm * 2048u + ((kb + akhi) ^ aswz);
                LDMATRIX_X4(afr[tm][0], afr[tm][1], afr[tm][2], afr[tm][3], addr);
            }
            uint32_t bfr[2][4];
#pragma unroll
            for (int tp = 0; tp < 2; tp++) {
                const int brow = wn + tp * 16 + b_rl;
                const uint32_t addr = bB + (uint32_t)brow * 128u +
                                      ((kb + bkhi) ^ (((uint32_t)brow & 7u) << 4));
                LDMATRIX_X4(bfr[tp][0], bfr[tp][1], bfr[tp][2], bfr[tp][3], addr);
            }
#pragma unroll
            for (int tm = 0; tm < 4; tm++)
#pragma unroll
                for (int tn = 0; tn < 4; tn++)
                    mma_f16(acc[tm][tn], afr[tm],
                            bfr[tn >> 1][(tn & 1) * 2 + 0],
                            bfr[tn >> 1][(tn & 1) * 2 + 1]);
        }
        st = (st + 1 >= 3) ? 0 : st + 1;
    }

#pragma unroll
    for (int tm = 0; tm < 4; tm++) {
#pragma unroll
        for (int tn = 0; tn < 4; tn++) {
            const int col = n0 + wn + tn * 8 + (lane & 3) * 2;
            const float bx = bias[col], by = bias[col + 1];
#pragma unroll
            for (int half_i = 0; half_i < 2; half_i++) {
                const int row = m0 + wm + tm * 16 + (lane >> 2) + half_i * 8;
                const float vx = acc[tm][tn][half_i * 2 + 0] + bx;
                const float vy = acc[tm][tn][half_i * 2 + 1] + by;
                if (MODE == 0) {
                    const int sel = col >> 10;
                    const int bb = row >> 10;
                    const int t  = row & 1023;
                    const int hh = (col & 1023) >> 6;
                    const int d  = col & 63;
                    if (sel == 2) {
                        __half* vt = g_vt + (size_t)(bb * H + hh) * DH * T;
                        vt[(size_t)d * T + t]       = __float2half_rn(vx);
                        vt[(size_t)(d + 1) * T + t] = __float2half_rn(vy);
                    } else {
                        __half* dst = (sel == 0) ? g_q : g_k;
                        *(__half2*)&dst[((size_t)(bb * H + hh) * T + t) * DH + d] =
                            __floats2half2_rn(vx, vy);
                    }
                } else {
                    float2 v; v.x = vx; v.y = vy;
                    *(float2*)&C[(size_t)row * Ntot + col] = v;
                }
            }
        }
    }
}

// ============================================================================
// Fused flash attention (R14 winner, exact): fp16 mma.sync, register-resident
// P, 2-buffer K/V double-buffering, fp32 adj via direct LDG.
// ============================================================================
constexpr int AQT = 128;
constexpr int AKT = 64;
constexpr int AOFF_Q  = 0;                      // [128 q][64 h] fp16
constexpr int AOFF_K0 = AOFF_Q  + 128 * 128;
constexpr int AOFF_K1 = AOFF_K0 + 64 * 128;
constexpr int AOFF_V0 = AOFF_K1 + 64 * 128;
constexpr int AOFF_V1 = AOFF_V0 + 64 * 128;
constexpr int AOFF_M0 = AOFF_V1 + 64 * 128;     // 64 floats
constexpr int AOFF_M1 = AOFF_M0 + 256;
constexpr int ATTN_SMEM_BYTES = AOFF_M1 + 256;  // 49,920 B

__device__ __forceinline__ void attn_load_tile(
    uint32_t sKb, uint32_t sVb, uint32_t sMb,
    const __half* __restrict__ kbase, const __half* __restrict__ vtbase,
    const float* __restrict__ mrow, int kk0, int tid)
{
#pragma unroll
    for (int it = 0; it < 2; it++) {
        const int idx = it * 256 + tid;
        const int r = idx >> 3, s = idx & 7;
        CP_ASYNC16(sKb + (uint32_t)r * 128u + (((uint32_t)s * 16u) ^ (((uint32_t)r & 7u) << 4)),
                   kbase + (size_t)(kk0 + r) * DH + s * 8);
    }
#pragma unroll
    for (int it = 0; it < 2; it++) {
        const int idx = it * 256 + tid;
        const int r = idx >> 3, s = idx & 7;
        CP_ASYNC16(sVb + (uint32_t)r * 128u + (((uint32_t)s * 16u) ^ (((uint32_t)r & 7u) << 4)),
                   vtbase + (size_t)r * T + kk0 + s * 8);
    }
    if (tid < 16)
        CP_ASYNC16(sMb + (uint32_t)tid * 16u, mrow + kk0 + tid * 4);
}

__global__ void __launch_bounds__(256, 2)
attn_mma_kernel(const float* __restrict__ adj, const float* __restrict__ mask)
{
    extern __shared__ __align__(1024) char smc[];

    const int b   = blockIdx.z;
    const int h   = blockIdx.y;
    const int q0g = blockIdx.x * AQT;
    const int tid = threadIdx.x;
    const int wid = tid >> 5;
    const int lane = tid & 31;
    const int q0  = wid * 16;

    const __half* qptr   = g_q  + ((size_t)(b * H + h) * T + q0g) * DH;
    const __half* kbase  = g_k  + (size_t)(b * H + h) * T * DH;
    const __half* vtbase = g_vt + (size_t)(b * H + h) * DH * T;
    const float*  aptr   = adj + ((size_t)b * T + q0g) * T;
    const float*  mrow   = mask + (size_t)b * T;

    const uint32_t sbase = smem_u32(smc);
    const uint32_t sQ = sbase + AOFF_Q;
    const uint32_t sK[2] = { sbase + AOFF_K0, sbase + AOFF_K1 };
    const uint32_t sV[2] = { sbase + AOFF_V0, sbase + AOFF_V1 };

    // ---- load Q once: fp16 -> scale by log2(e)/8 -> fp16, swizzled rows ----
#pragma unroll
    for (int it = 0; it < 4; it++) {
        const int idx = it * 256 + tid;
        const int r = idx >> 3, s = idx & 7;
        const __half2* src = (const __half2*)(qptr + (size_t)r * DH + s * 8);
        uint32_t out[4];
#pragma unroll
        for (int j = 0; j < 4; j++) {
            float2 f = __half22float2(src[j]);
            __half2 hv = __floats2half2_rn(f.x * QSCALE, f.y * QSCALE);
            out[j] = *(uint32_t*)&hv;
        }
        *(uint4*)(smc + r * 128 + (((uint32_t)s * 16u) ^ (((uint32_t)r & 7u) << 4))) =
            make_uint4(out[0], out[1], out[2], out[3]);
    }

    attn_load_tile(sK[0], sV[0], sbase + AOFF_M0, kbase, vtbase, mrow, 0, tid);
    CP_COMMIT();

    const int      a_row    = q0 + (lane & 15);
    const uint32_t a_off    = (uint32_t)a_row * 128u;
    const uint32_t a_swz    = ((uint32_t)a_row & 7u) << 4;
    const uint32_t a_khi    = (uint32_t)(lane & 16);
    const int      b_rl     = (lane & 7) + ((lane & 16) >> 1);
    const uint32_t b_khi    = (uint32_t)((lane & 8) << 1);

    const int rq_lo = q0 + (lane >> 2);
    const int ccol0 = (lane & 3) * 2;

    __syncthreads();   // Q stores visible

    // ---- hoist Q fragments (4 x k16 over DH=64) ----
    uint32_t qfr[4][4];
#pragma unroll
    for (int ks = 0; ks < 4; ks++) {
        LDMATRIX_X4(qfr[ks][0], qfr[ks][1], qfr[ks][2], qfr[ks][3],
                    sQ + a_off + (((uint32_t)ks * 32u + a_khi) ^ a_swz));
    }

    float oacc[8][4];
#pragma unroll
    for (int tn = 0; tn < 8; tn++)
#pragma unroll
        for (int e = 0; e < 4; e++) oacc[tn][e] = 0.f;
    float l1[2] = { 0.f, 0.f };
    float l2[2] = { 0.f, 0.f };

    constexpr int NT = T / AKT;

    for (int kt = 0; kt < NT; kt++) {
        const int cur = kt & 1;
        const int kk0 = kt * AKT;

        CP_WAIT(0);
        __syncthreads();

        // adj -> registers early (consumed after S-mma)
        float2 areg[2][8];
#pragma unroll
        for (int hh = 0; hh < 2; hh++) {
            const float* arow = aptr + (size_t)(rq_lo + 8 * hh) * T + kk0 + ccol0;
#pragma unroll
            for (int tn = 0; tn < 8; tn++)
                areg[hh][tn] = *(const float2*)(arow + tn * 8);
        }

        if (kt + 1 < NT) {
            attn_load_tile(sK[1 - cur], sV[1 - cur],
                           sbase + (cur ? AOFF_M0 : AOFF_M1),
                           kbase, vtbase, mrow, (kt + 1) * AKT, tid);
        }
        CP_COMMIT();

        const uint32_t sKb = sK[cur];
        const uint32_t sVb = sV[cur];
        const float* Ms = (const float*)(smc + (cur ? AOFF_M1 : AOFF_M0));

        float2 mreg[8];
#pragma unroll
        for (int tn = 0; tn < 8; tn++)
            mreg[tn] = *(const float2*)&Ms[tn * 8 + ccol0];

        // ---- S = Q @ K^T : 4 k16-steps, 8 n-tiles ----
        float sacc[8][4];
#pragma unroll
        for (int tn = 0; tn < 8; tn++)
#pragma unroll
            for (int e = 0; e < 4; e++) sacc[tn][e] = 0.f;

#pragma unroll
        for (int ks = 0; ks < 4; ks++) {
            const uint32_t kb = (uint32_t)ks * 32u;
            uint32_t kf[4][4];
#pragma unroll
            for (int tp = 0; tp < 4; tp++) {
                const uint32_t row = (uint32_t)(tp * 16 + b_rl);
                LDMATRIX_X4(kf[tp][0], kf[tp][1], kf[tp][2], kf[tp][3],
                            sKb + row * 128u + ((kb + b_khi) ^ ((row & 7u) << 4)));
            }
#pragma unroll
            for (int tn = 0; tn < 8; tn++)
                mma_f16(sacc[tn], qfr[ks],
                        kf[tn >> 1][(tn & 1) * 2 + 0],
                        kf[tn >> 1][(tn & 1) * 2 + 1]);
        }

        // ---- softmax -> P in REGISTERS -> PV mma (per k16 group g) ----
#pragma unroll
        for (int g = 0; g < 4; g++) {
            uint32_t pa[4];
#pragma unroll
            for (int u = 0; u < 2; u++) {
                const int tn = g * 2 + u;
#pragma unroll
                for (int hh = 0; hh < 2; hh++) {
                    const float p0 = ex2(sacc[tn][2 * hh + 0] * areg[hh][tn].x * mreg[tn].x);
                    const float p1 = ex2(sacc[tn][2 * hh + 1] * areg[hh][tn].y * mreg[tn].y);
                    const float pm0 = p0 * mreg[tn].x;
                    const float pm1 = p1 * mreg[tn].y;
                    l2[hh] += p0 + p1;
                    l1[hh] += pm0 + pm1;
                    const __half2 pw = __floats2half2_rn(pm0, pm1);
                    pa[u * 2 + hh] = *(const uint32_t*)&pw;
                }
            }

            const uint32_t kb = (uint32_t)g * 32u;
            uint32_t vf[4][4];
#pragma unroll
            for (int tp = 0; tp < 4; tp++) {
                const uint32_t row = (uint32_t)(tp * 16 + b_rl);
                LDMATRIX_X4(vf[tp][0], vf[tp][1], vf[tp][2], vf[tp][3],
                            sVb + row * 128u + ((kb + b_khi) ^ ((row & 7u) << 4)));
            }
#pragma unroll
            for (int tn = 0; tn < 8; tn++)
                mma_f16(oacc[tn], pa,
                        vf[tn >> 1][(tn & 1) * 2 + 0],
                        vf[tn >> 1][(tn & 1) * 2 + 1]);
        }
    }

    // ---- one-time l1/l2 reduction over the 4-lane row group ----
#pragma unroll
    for (int hh = 0; hh < 2; hh++) {
        l1[hh] += __shfl_xor_sync(0xffffffffu, l1[hh], 1);
        l1[hh] += __shfl_xor_sync(0xffffffffu, l1[hh], 2);
        l2[hh] += __shfl_xor_sync(0xffffffffu, l2[hh], 1);
        l2[hh] += __shfl_xor_sync(0xffffffffu, l2[hh], 2);
    }

    // ---- normalize, fp16, write ctx ----
#pragma unroll
    for (int hh = 0; hh < 2; hh++) {
        const float inv = 1.0f / (l1[hh] + EPS * l2[hh]);
        const int gq = q0g + rq_lo + 8 * hh;
#pragma unroll
        for (int tn = 0; tn < 8; tn++) {
            const int d = tn * 8 + ccol0;
            *(__half2*)&g_ctx[(size_t)(b * T + gq) * D + h * DH + d] =
                __floats2half2_rn(oacc[tn][2 * hh + 0] * inv,
                                  oacc[tn][2 * hh + 1] * inv);
        }
    }
}

// ============================================================================
// launch
// ============================================================================
extern "C" void kernel_launch(void* const* d_in, const int* in_sizes, int n_in,
                              void* d_out, int out_size)
{
    (void)in_sizes; (void)n_in; (void)out_size;
    const float* inputs = (const float*)d_in[0];
    const float* mask   = (const float*)d_in[1];
    const float* adj    = (const float*)d_in[2];
    const float* W_qkv  = (const float*)d_in[3];
    const float* b_qkv  = (const float*)d_in[4];
    const float* W_out  = (const float*)d_in[5];
    const float* b_out  = (const float*)d_in[6];
    float* out = (float*)d_out;

    cudaFuncSetAttribute(gemm_mma_kernel<0>,
                         cudaFuncAttributeMaxDynamicSharedMemorySize,
                         GEMM_SMEM_BYTES);
    cudaFuncSetAttribute(gemm_mma_kernel<1>,
                         cudaFuncAttributeMaxDynamicSharedMemorySize,
                         GEMM_SMEM_BYTES);
    cudaFuncSetAttribute(attn_mma_kernel,
                         cudaFuncAttributeMaxDynamicSharedMemorySize,
                         ATTN_SMEM_BYTES);

    __half *p_in_h, *p_wqkv_h, *p_wout_h;
    cudaGetSymbolAddress((void**)&p_in_h,   g_in_h);
    cudaGetSymbolAddress((void**)&p_wqkv_h, g_wqkv_h);
    cudaGetSymbolAddress((void**)&p_wout_h, g_wout_h);

    dim3 blk256(256);

    // fp32 -> fp16 conversion
    {
        const int n4_in   = (B * T * D) / 4;
        const int n4_wqkv = (3 * D * D) / 4;
        const int n4_wout = (D * D) / 4;
        f2h_kernel<<<(n4_in   + 255) / 256, blk256>>>((const float4*)inputs, (__half2*)p_in_h,   n4_in);
        f2h_kernel<<<(n4_wqkv + 255) / 256, blk256>>>((const float4*)W_qkv,  (__half2*)p_wqkv_h, n4_wqkv);
        f2h_kernel<<<(n4_wout + 255) / 256, blk256>>>((const float4*)W_out,  (__half2*)p_wout_h, n4_wout);
    }

    // QKV projection: M=8192, N=3072, K=1024 (fp16 mma.sync)
    gemm_mma_kernel<0><<<dim3((3 * D) / 128, (B * T) / 128), blk256, GEMM_SMEM_BYTES>>>(
        p_in_h, p_wqkv_h, b_qkv, nullptr, D, 3 * D);

    // fused attention (fp16 mma.sync, register-resident P)
    attn_mma_kernel<<<dim3(T / AQT, H, B), blk256, ATTN_SMEM_BYTES>>>(adj, mask);

    // output projection: M=8192, N=1024, K=1024 (fp16 mma.sync)
    gemm_mma_kernel<1><<<dim3(D / 128, (B * T) / 128), blk256, GEMM_SMEM_BYTES>>>(
        nullptr, p_wout_h, b_out, out, D, D);
}